// round 6
// baseline (speedup 1.0000x reference)
#include <cuda_runtime.h>

#define NIMG 96
#define HH 512
#define WW 512
#define HS 256   // cA resolution
#define WS 256

typedef unsigned long long ull;

__device__ __forceinline__ ull pk2(float lo, float hi) {
    ull r; asm("mov.b64 %0, {%1, %2};" : "=l"(r) : "f"(lo), "f"(hi)); return r;
}
__device__ __forceinline__ void upk2(ull v, float& lo, float& hi) {
    asm("mov.b64 {%0, %1}, %2;" : "=f"(lo), "=f"(hi) : "l"(v));
}
__device__ __forceinline__ void fma2(ull& d, ull a, ull b) {
    asm("fma.rn.f32x2 %0, %1, %2, %0;" : "+l"(d) : "l"(a), "l"(b));
}

// Scratch: only cA survives between kernels
__device__ float g_cA[NIMG * HS * WS];   // 25.2 MB

// ---------------------------------------------------------------------------
// Kernel 1: Haar DWT. cA -> g_cA, cH/cV -> d_out "high" region directly.
// (HBM-bound at roofline; unchanged.)
// ---------------------------------------------------------------------------
__global__ void dwt_kernel(const float* __restrict__ x, float* __restrict__ high) {
    int i   = blockIdx.x;
    int img = blockIdx.y;
    int t   = threadIdx.x;

    const float4* r0 = (const float4*)(x + ((size_t)img * HH + 2 * i) * WW);
    const float4* r1 = r0 + (WW / 4);
    float4 t0 = r0[t];
    float4 t1 = r1[t];

    float a0 = t0.x, b0 = t0.y, c0 = t1.x, d0 = t1.y;
    float a1 = t0.z, b1 = t0.w, c1 = t1.z, d1 = t1.w;

    float2 vA = make_float2(0.5f * (a0 + b0 + c0 + d0), 0.5f * (a1 + b1 + c1 + d1));
    float2 vH = make_float2(0.5f * (a0 + b0 - c0 - d0), 0.5f * (a1 + b1 - c1 - d1));
    float2 vV = make_float2(0.5f * (a0 - b0 + c0 - d0), 0.5f * (a1 - b1 + c1 - d1));

    size_t oA = (size_t)img * HS * WS + (size_t)i * WS + 2 * t;
    *(float2*)(g_cA + oA) = vA;

    size_t oH = (size_t)img * (2 * HS * WS) + (size_t)i * WS + 2 * t;
    *(float2*)(high + oH) = vH;
    *(float2*)(high + oH + HS * WS) = vV;
}

// ---------------------------------------------------------------------------
// conv1 stage: one input channel ic -> one 34x(34+2) s1 tile in smem.
// 4-wide outputs: each task computes s1[r][4cg .. 4cg+3] from a 4x10 strip.
// Row-streamed accumulation (low register liveness). Even f32x2 pairs come
// straight from LDS.64 float2 loads (pack-movs eliminated by ptxas).
// ---------------------------------------------------------------------------
__device__ __forceinline__ void conv1_stage(
    const float (*cAt)[76], float (*dst)[36],
    const float* w1s, float bias, int ic, int tid,
    int r0s, int c0s, bool interior)
{
    ull wq[9];
#pragma unroll
    for (int k = 0; k < 9; k++) { float w = w1s[ic * 9 + k]; wq[k] = pk2(w, w); }

    for (int g = tid; g < 306; g += 256) {
        int r  = g / 9;
        int cg = g - 9 * r;
        int c0 = 4 * cg;
        const float* base = &cAt[2 * r][8 * cg];

        // acc[dy][pair]: conv rows (2r+dy), conv col pairs (2p, 2p+1)
        ull a[2][4];
#pragma unroll
        for (int p = 0; p < 4; p++) { a[0][p] = 0ull; a[1][p] = 0ull; }

#pragma unroll
        for (int i = 0; i < 4; i++) {        // input row 2r + i
            float2 q[5];
#pragma unroll
            for (int m = 0; m < 5; m++) q[m] = *(const float2*)(base + i * 76 + 2 * m);
            ull pr[9];
#pragma unroll
            for (int j = 0; j < 9; j++)
                pr[j] = (j & 1) ? pk2(q[j >> 1].y, q[(j >> 1) + 1].x)
                                : pk2(q[j >> 1].x, q[j >> 1].y);
#pragma unroll
            for (int kx = 0; kx < 3; kx++) {
                if (i < 3) {                  // contributes to dy=0 with ky=i
                    ull w = wq[3 * i + kx];
#pragma unroll
                    for (int p = 0; p < 4; p++) fma2(a[0][p], w, pr[2 * p + kx]);
                }
                if (i > 0) {                  // contributes to dy=1 with ky=i-1
                    ull w = wq[3 * (i - 1) + kx];
#pragma unroll
                    for (int p = 0; p < 4; p++) fma2(a[1][p], w, pr[2 * p + kx]);
                }
            }
        }

        float mv[4];
#pragma unroll
        for (int o = 0; o < 4; o++) {
            float l0, h0, l1, h1;
            upk2(a[0][o], l0, h0);
            upk2(a[1][o], l1, h1);
            float mm = fmaxf(fmaxf(l0, h0), fmaxf(l1, h1));
            mm = fmaxf(mm + bias, 0.f);       // max(relu(x+b)) == relu(max(x)+b)
            if (!interior) {
                int rs = r0s + r, cs = c0s + c0 + o;
                if ((unsigned)rs >= 128u || (unsigned)cs >= 128u) mm = 0.f;
            }
            mv[o] = mm;
        }
        *(float2*)&dst[r][c0]     = make_float2(mv[0], mv[1]);
        *(float2*)&dst[r][c0 + 2] = make_float2(mv[2], mv[3]);
    }
}

// ---------------------------------------------------------------------------
// conv2 stage: accumulate one input channel into the 8-oc (4 ull-pair) accs.
// ---------------------------------------------------------------------------
__device__ __forceinline__ void conv2_stage(
    const float (*src)[36], const ull* __restrict__ wrow,
    int tx, int ty, ull acc[4][4])
{
    float p[4][4];
#pragma unroll
    for (int i = 0; i < 4; i++) {
        float2 v0 = *(const float2*)&src[2 * ty + i][2 * tx];
        float2 v1 = *(const float2*)&src[2 * ty + i][2 * tx + 2];
        p[i][0] = v0.x; p[i][1] = v0.y; p[i][2] = v1.x; p[i][3] = v1.y;
    }
    ull pb[4][4];
#pragma unroll
    for (int i = 0; i < 4; i++)
#pragma unroll
        for (int j = 0; j < 4; j++) pb[i][j] = pk2(p[i][j], p[i][j]);

#pragma unroll
    for (int ky = 0; ky < 3; ky++)
#pragma unroll
        for (int kx = 0; kx < 3; kx++) {
            ull w0 = wrow[(ky * 3 + kx) * 4 + 0];
            ull w1 = wrow[(ky * 3 + kx) * 4 + 1];
            ull w2 = wrow[(ky * 3 + kx) * 4 + 2];
            ull w3 = wrow[(ky * 3 + kx) * 4 + 3];
#pragma unroll
            for (int dy = 0; dy < 2; dy++)
#pragma unroll
                for (int dx = 0; dx < 2; dx++) {
                    ull pv = pb[dy + ky][dx + kx];
                    int q = dy * 2 + dx;
                    fma2(acc[q][0], w0, pv);
                    fma2(acc[q][1], w1, pv);
                    fma2(acc[q][2], w2, pv);
                    fma2(acc[q][3], w3, pv);
                }
        }
}

// ---------------------------------------------------------------------------
// Kernel 2: FUSED conv1+relu+pool -> conv2+relu+pool -> conv3(1x1).
// Double-buffered s1 tile: 2 conv1 channels per sync round (16 barriers).
// ---------------------------------------------------------------------------
__global__ void __launch_bounds__(256) fused_kernel(
    const float* __restrict__ w1, const float* __restrict__ b1,
    const float* __restrict__ w2, const float* __restrict__ b2,
    const float* __restrict__ w3, const float* __restrict__ b3,
    float* __restrict__ low)
{
    __shared__ __align__(16) float cAt[70][76];      // 21.3 KB
    __shared__ __align__(16) float s1t[2][34][36];   //  9.8 KB
    __shared__ ull   w2p[16 * 9 * 4];                //  4.6 KB
    __shared__ float w1s[16 * 9];
    __shared__ float b1s[16];
    __shared__ float b2s[8];
    __shared__ float w3s[32];
    __shared__ float b3s[4];

    const int tx = threadIdx.x, ty = threadIdx.y;
    const int tid = ty * 16 + tx;
    const int px0 = blockIdx.x * 16, py0 = blockIdx.y * 16;  // pooled-64 origin
    const int img = blockIdx.z;

    // ---- weights to smem ----
    if (tid < 144) w1s[tid] = w1[tid];
    if (tid < 16)  b1s[tid] = b1[tid];
    if (tid < 8)   b2s[tid] = b2[tid];
    if (tid < 32)  w3s[tid] = w3[tid];
    if (tid < 4)   b3s[tid] = b3[tid];
    for (int idx = tid; idx < 16 * 9 * 4; idx += 256) {
        int ocp = idx & 3;
        int k   = (idx >> 2) % 9;
        int ic  = idx / 36;
        int oc0 = 2 * ocp;
        float lo = w2[(oc0 * 16 + ic) * 9 + k];
        float hi = w2[((oc0 + 1) * 16 + ic) * 9 + k];
        w2p[idx] = pk2(lo, hi);
    }

    // ---- cA tile: 70x70 at origin (4*py0-3, 4*px0-3), zero-padded ----
    {
        const float* in = g_cA + (size_t)img * HS * WS;
        const int gr0 = 4 * py0 - 3, gc0 = 4 * px0 - 3;
        int r = tid / 70, c = tid - 70 * r;
        for (int k = tid; k < 70 * 70; k += 256) {
            int ir = gr0 + r, ic = gc0 + c;
            float v = 0.f;
            if ((unsigned)ir < (unsigned)HS && (unsigned)ic < (unsigned)WS)
                v = in[(size_t)ir * WS + ic];
            cAt[r][c] = v;
            c += 46; r += 3;                 // advance by 256 = 3*70 + 46
            if (c >= 70) { c -= 70; r++; }
        }
    }

    const int r0s = 2 * py0 - 1, c0s = 2 * px0 - 1;  // s1-tile global origin
    const bool interior = (py0 == 16 || py0 == 32) && (px0 == 16 || px0 == 32);

    ull acc[4][4];
#pragma unroll
    for (int q = 0; q < 4; q++)
#pragma unroll
        for (int p = 0; p < 4; p++) acc[q][p] = 0ull;

    for (int ic = 0; ic < 16; ic += 2) {
        __syncthreads();   // s1t buffers free (covers initial smem fill too)
        conv1_stage((const float(*)[76])cAt, s1t[0], w1s, b1s[ic],     ic,     tid, r0s, c0s, interior);
        conv1_stage((const float(*)[76])cAt, s1t[1], w1s, b1s[ic + 1], ic + 1, tid, r0s, c0s, interior);
        __syncthreads();
        conv2_stage((const float(*)[36])s1t[0], &w2p[ic * 36],       tx, ty, acc);
        conv2_stage((const float(*)[36])s1t[1], &w2p[(ic + 1) * 36], tx, ty, acc);
    }

    // ---- epilogue: bias + pool-max + relu, then 1x1 conv3 ----
    float r8[8];
#pragma unroll
    for (int p = 0; p < 4; p++) {
        float lo0, hi0, lo1, hi1, lo2, hi2, lo3, hi3;
        upk2(acc[0][p], lo0, hi0);
        upk2(acc[1][p], lo1, hi1);
        upk2(acc[2][p], lo2, hi2);
        upk2(acc[3][p], lo3, hi3);
        float mlo = fmaxf(fmaxf(lo0, lo1), fmaxf(lo2, lo3));
        float mhi = fmaxf(fmaxf(hi0, hi1), fmaxf(hi2, hi3));
        r8[2 * p]     = fmaxf(mlo + b2s[2 * p], 0.f);
        r8[2 * p + 1] = fmaxf(mhi + b2s[2 * p + 1], 0.f);
    }

    const int oy = py0 + ty, ox = px0 + tx;
    const int pix = oy * 64 + ox;
#pragma unroll
    for (int oc = 0; oc < 4; oc++) {
        float s = b3s[oc];
#pragma unroll
        for (int ic = 0; ic < 8; ic++) s = fmaf(w3s[oc * 8 + ic], r8[ic], s);
        low[((size_t)img * 4 + oc) * 4096 + pix] = s;
    }
}

// ---------------------------------------------------------------------------
extern "C" void kernel_launch(void* const* d_in, const int* in_sizes, int n_in,
                              void* d_out, int out_size) {
    const float* x  = (const float*)d_in[0];
    const float* w1 = (const float*)d_in[1];
    const float* b1 = (const float*)d_in[2];
    const float* w2 = (const float*)d_in[3];
    const float* b2 = (const float*)d_in[4];
    const float* w3 = (const float*)d_in[5];
    const float* b3 = (const float*)d_in[6];

    float* out  = (float*)d_out;
    float* low  = out;                    // 96*4*64*64 = 1,572,864 floats
    float* high = out + 1572864;          // 96*2*256*256 = 12,582,912 floats

    dwt_kernel<<<dim3(256, 96), 128>>>(x, high);
    fused_kernel<<<dim3(4, 4, NIMG), dim3(16, 16)>>>(w1, b1, w2, b2, w3, b3, low);
}

// round 8
// speedup vs baseline: 1.2618x; 1.2618x over previous
#include <cuda_runtime.h>

#define NIMG 96
#define HH 512
#define WW 512
#define HS 256   // cA resolution
#define WS 256

typedef unsigned long long ull;

__device__ __forceinline__ ull pk2(float lo, float hi) {
    ull r; asm("mov.b64 %0, {%1, %2};" : "=l"(r) : "f"(lo), "f"(hi)); return r;
}
__device__ __forceinline__ void upk2(ull v, float& lo, float& hi) {
    asm("mov.b64 {%0, %1}, %2;" : "=f"(lo), "=f"(hi) : "l"(v));
}
__device__ __forceinline__ void fma2(ull& d, ull a, ull b) {
    asm("fma.rn.f32x2 %0, %1, %2, %0;" : "+l"(d) : "l"(a), "l"(b));
}

// Scratch: only cA survives between kernels
__device__ float g_cA[NIMG * HS * WS];   // 25.2 MB

// ---------------------------------------------------------------------------
// Kernel 1: Haar DWT. cA -> g_cA, cH/cV -> d_out "high" region directly.
// (HBM-bound at roofline; unchanged.)
// ---------------------------------------------------------------------------
__global__ void dwt_kernel(const float* __restrict__ x, float* __restrict__ high) {
    int i   = blockIdx.x;
    int img = blockIdx.y;
    int t   = threadIdx.x;

    const float4* r0 = (const float4*)(x + ((size_t)img * HH + 2 * i) * WW);
    const float4* r1 = r0 + (WW / 4);
    float4 t0 = r0[t];
    float4 t1 = r1[t];

    float a0 = t0.x, b0 = t0.y, c0 = t1.x, d0 = t1.y;
    float a1 = t0.z, b1 = t0.w, c1 = t1.z, d1 = t1.w;

    float2 vA = make_float2(0.5f * (a0 + b0 + c0 + d0), 0.5f * (a1 + b1 + c1 + d1));
    float2 vH = make_float2(0.5f * (a0 + b0 - c0 - d0), 0.5f * (a1 + b1 - c1 - d1));
    float2 vV = make_float2(0.5f * (a0 - b0 + c0 - d0), 0.5f * (a1 - b1 + c1 - d1));

    size_t oA = (size_t)img * HS * WS + (size_t)i * WS + 2 * t;
    *(float2*)(g_cA + oA) = vA;

    size_t oH = (size_t)img * (2 * HS * WS) + (size_t)i * WS + 2 * t;
    *(float2*)(high + oH) = vH;
    *(float2*)(high + oH + HS * WS) = vV;
}

// ---------------------------------------------------------------------------
// conv1 stage: one input channel -> one 34x36 s1 tile in smem.
// One pooled output per task; dx packed in f32x2. Input rows streamed:
// per row only 2 LDS.64 + 1 pack, 3 ull live (low register pressure).
// ---------------------------------------------------------------------------
__device__ __forceinline__ void conv1_stage(
    const float (*cAt)[72], float (*dst)[36],
    const ull* wq, ull biasq, int tid,
    int r0s, int c0s, bool interior)
{
    int r = tid / 34, c = tid - 34 * r;
    for (int k = tid; k < 34 * 34; k += 256) {
        const float* base = &cAt[2 * r][2 * c];

        ull a0 = biasq, a1 = biasq;   // dy=0 / dy=1, dx pair packed
#pragma unroll
        for (int i = 0; i < 4; i++) {          // input row 2r + i
            float2 q0 = *(const float2*)(base + i * 72);
            float2 q1 = *(const float2*)(base + i * 72 + 2);
            ull p0 = pk2(q0.x, q0.y);          // even pair: direct from LDS.64
            ull p1 = pk2(q0.y, q1.x);
            ull p2 = pk2(q1.x, q1.y);
            if (i < 3) {                        // ky = i for dy=0
                fma2(a0, wq[3 * i + 0], p0);
                fma2(a0, wq[3 * i + 1], p1);
                fma2(a0, wq[3 * i + 2], p2);
            }
            if (i > 0) {                        // ky = i-1 for dy=1
                fma2(a1, wq[3 * (i - 1) + 0], p0);
                fma2(a1, wq[3 * (i - 1) + 1], p1);
                fma2(a1, wq[3 * (i - 1) + 2], p2);
            }
        }

        float l0, h0, l1, h1;
        upk2(a0, l0, h0);
        upk2(a1, l1, h1);
        float m = fmaxf(fmaxf(l0, h0), fmaxf(l1, h1));
        m = fmaxf(m, 0.f);
        if (!interior) {
            int rs = r0s + r, cs = c0s + c;
            if ((unsigned)rs >= 128u || (unsigned)cs >= 128u) m = 0.f;
        }
        dst[r][c] = m;

        c += 18; r += 7;                        // advance 256 = 7*34 + 18
        if (c >= 34) { c -= 34; r++; }
    }
}

// ---------------------------------------------------------------------------
// conv2 stage: accumulate one input channel. Rolling 2-row broadcast buffer
// (16 regs) instead of full 4x4 broadcast block (32 regs). Weights loaded
// once per (ky,kx) from prepacked smem.
// ---------------------------------------------------------------------------
__device__ __forceinline__ void conv2_stage(
    const float (*src)[36], const ull* __restrict__ wrow,
    int tx, int ty, ull acc[4][4])
{
    ull rA[4], rB[4];
    {
        float2 v0 = *(const float2*)&src[2 * ty][2 * tx];
        float2 v1 = *(const float2*)&src[2 * ty][2 * tx + 2];
        rA[0] = pk2(v0.x, v0.x); rA[1] = pk2(v0.y, v0.y);
        rA[2] = pk2(v1.x, v1.x); rA[3] = pk2(v1.y, v1.y);
    }
#pragma unroll
    for (int ky = 0; ky < 3; ky++) {
        ull* top = (ky & 1) ? rB : rA;
        ull* bot = (ky & 1) ? rA : rB;
        {
            float2 v0 = *(const float2*)&src[2 * ty + ky + 1][2 * tx];
            float2 v1 = *(const float2*)&src[2 * ty + ky + 1][2 * tx + 2];
            bot[0] = pk2(v0.x, v0.x); bot[1] = pk2(v0.y, v0.y);
            bot[2] = pk2(v1.x, v1.x); bot[3] = pk2(v1.y, v1.y);
        }
#pragma unroll
        for (int kx = 0; kx < 3; kx++) {
            ull w0 = wrow[(ky * 3 + kx) * 4 + 0];
            ull w1 = wrow[(ky * 3 + kx) * 4 + 1];
            ull w2 = wrow[(ky * 3 + kx) * 4 + 2];
            ull w3 = wrow[(ky * 3 + kx) * 4 + 3];
#pragma unroll
            for (int dx = 0; dx < 2; dx++) {
                ull pt = top[dx + kx];          // dy=0 uses row ky
                ull pb = bot[dx + kx];          // dy=1 uses row ky+1
                fma2(acc[dx][0], w0, pt);
                fma2(acc[dx][1], w1, pt);
                fma2(acc[dx][2], w2, pt);
                fma2(acc[dx][3], w3, pt);
                fma2(acc[2 + dx][0], w0, pb);
                fma2(acc[2 + dx][1], w1, pb);
                fma2(acc[2 + dx][2], w2, pb);
                fma2(acc[2 + dx][3], w3, pb);
            }
        }
    }
}

// ---------------------------------------------------------------------------
// Kernel 2: FUSED conv1+relu+pool -> conv2+relu+pool -> conv3(1x1).
// 64-reg cap for 4 CTAs/SM. Double-buffered s1 tile (16 barriers).
// ---------------------------------------------------------------------------
__global__ void __launch_bounds__(256, 4) fused_kernel(
    const float* __restrict__ w1, const float* __restrict__ b1,
    const float* __restrict__ w2, const float* __restrict__ b2,
    const float* __restrict__ w3, const float* __restrict__ b3,
    float* __restrict__ low)
{
    __shared__ __align__(16) float cAt[70][72];      // 20.2 KB
    __shared__ __align__(16) float s1t[2][34][36];   //  9.8 KB
    __shared__ ull   w2p[16 * 9 * 4];                //  4.6 KB
    __shared__ float w1s[16 * 9];
    __shared__ float b1s[16];
    __shared__ float b2s[8];
    __shared__ float w3s[32];
    __shared__ float b3s[4];

    const int tx = threadIdx.x, ty = threadIdx.y;
    const int tid = ty * 16 + tx;
    const int px0 = blockIdx.x * 16, py0 = blockIdx.y * 16;  // pooled-64 origin
    const int img = blockIdx.z;

    // ---- weights to smem ----
    if (tid < 144) w1s[tid] = w1[tid];
    if (tid < 16)  b1s[tid] = b1[tid];
    if (tid < 8)   b2s[tid] = b2[tid];
    if (tid < 32)  w3s[tid] = w3[tid];
    if (tid < 4)   b3s[tid] = b3[tid];
    for (int idx = tid; idx < 16 * 9 * 4; idx += 256) {
        int ocp = idx & 3;
        int k   = (idx >> 2) % 9;
        int ic  = idx / 36;
        int oc0 = 2 * ocp;
        float lo = w2[(oc0 * 16 + ic) * 9 + k];
        float hi = w2[((oc0 + 1) * 16 + ic) * 9 + k];
        w2p[idx] = pk2(lo, hi);
    }

    // ---- cA tile: 70x70 at origin (4*py0-3, 4*px0-3), zero-padded ----
    {
        const float* in = g_cA + (size_t)img * HS * WS;
        const int gr0 = 4 * py0 - 3, gc0 = 4 * px0 - 3;
        int r = tid / 70, c = tid - 70 * r;
        for (int k = tid; k < 70 * 70; k += 256) {
            int ir = gr0 + r, ic = gc0 + c;
            float v = 0.f;
            if ((unsigned)ir < (unsigned)HS && (unsigned)ic < (unsigned)WS)
                v = in[(size_t)ir * WS + ic];
            cAt[r][c] = v;
            c += 46; r += 3;                 // advance 256 = 3*70 + 46
            if (c >= 70) { c -= 70; r++; }
        }
    }

    const int r0s = 2 * py0 - 1, c0s = 2 * px0 - 1;  // s1-tile global origin
    const bool interior = (py0 == 16 || py0 == 32) && (px0 == 16 || px0 == 32);

    ull acc[4][4];
#pragma unroll
    for (int q = 0; q < 4; q++)
#pragma unroll
        for (int p = 0; p < 4; p++) acc[q][p] = 0ull;

    for (int ic = 0; ic < 16; ic += 2) {
        __syncthreads();   // s1t buffers free (covers initial smem fill too)
        {
            ull wq[9];
#pragma unroll
            for (int k = 0; k < 9; k++) { float w = w1s[ic * 9 + k]; wq[k] = pk2(w, w); }
            float b = b1s[ic];
            conv1_stage((const float(*)[72])cAt, s1t[0], wq, pk2(b, b), tid, r0s, c0s, interior);
        }
        {
            ull wq[9];
#pragma unroll
            for (int k = 0; k < 9; k++) { float w = w1s[(ic + 1) * 9 + k]; wq[k] = pk2(w, w); }
            float b = b1s[ic + 1];
            conv1_stage((const float(*)[72])cAt, s1t[1], wq, pk2(b, b), tid, r0s, c0s, interior);
        }
        __syncthreads();
        conv2_stage((const float(*)[36])s1t[0], &w2p[ic * 36],       tx, ty, acc);
        conv2_stage((const float(*)[36])s1t[1], &w2p[(ic + 1) * 36], tx, ty, acc);
    }

    // ---- epilogue: bias + pool-max + relu, then 1x1 conv3 ----
    float r8[8];
#pragma unroll
    for (int p = 0; p < 4; p++) {
        float lo0, hi0, lo1, hi1, lo2, hi2, lo3, hi3;
        upk2(acc[0][p], lo0, hi0);
        upk2(acc[1][p], lo1, hi1);
        upk2(acc[2][p], lo2, hi2);
        upk2(acc[3][p], lo3, hi3);
        float mlo = fmaxf(fmaxf(lo0, lo1), fmaxf(lo2, lo3));
        float mhi = fmaxf(fmaxf(hi0, hi1), fmaxf(hi2, hi3));
        r8[2 * p]     = fmaxf(mlo + b2s[2 * p], 0.f);
        r8[2 * p + 1] = fmaxf(mhi + b2s[2 * p + 1], 0.f);
    }

    const int oy = py0 + ty, ox = px0 + tx;
    const int pix = oy * 64 + ox;
#pragma unroll
    for (int oc = 0; oc < 4; oc++) {
        float s = b3s[oc];
#pragma unroll
        for (int ic = 0; ic < 8; ic++) s = fmaf(w3s[oc * 8 + ic], r8[ic], s);
        low[((size_t)img * 4 + oc) * 4096 + pix] = s;
    }
}

// ---------------------------------------------------------------------------
extern "C" void kernel_launch(void* const* d_in, const int* in_sizes, int n_in,
                              void* d_out, int out_size) {
    const float* x  = (const float*)d_in[0];
    const float* w1 = (const float*)d_in[1];
    const float* b1 = (const float*)d_in[2];
    const float* w2 = (const float*)d_in[3];
    const float* b2 = (const float*)d_in[4];
    const float* w3 = (const float*)d_in[5];
    const float* b3 = (const float*)d_in[6];

    float* out  = (float*)d_out;
    float* low  = out;                    // 96*4*64*64 = 1,572,864 floats
    float* high = out + 1572864;          // 96*2*256*256 = 12,582,912 floats

    dwt_kernel<<<dim3(256, 96), 128>>>(x, high);
    fused_kernel<<<dim3(4, 4, NIMG), dim3(16, 16)>>>(w1, b1, w2, b2, w3, b3, low);
}

// round 9
// speedup vs baseline: 1.4574x; 1.1550x over previous
#include <cuda_runtime.h>

#define NIMG 96
#define HH 512
#define WW 512
#define HS 256   // cA resolution
#define WS 256

typedef unsigned long long ull;

__device__ __forceinline__ ull pk2(float lo, float hi) {
    ull r; asm("mov.b64 %0, {%1, %2};" : "=l"(r) : "f"(lo), "f"(hi)); return r;
}
__device__ __forceinline__ void upk2(ull v, float& lo, float& hi) {
    asm("mov.b64 {%0, %1}, %2;" : "=f"(lo), "=f"(hi) : "l"(v));
}
__device__ __forceinline__ void fma2(ull& d, ull a, ull b) {
    asm("fma.rn.f32x2 %0, %1, %2, %0;" : "+l"(d) : "l"(a), "l"(b));
}

// Scratch: only cA survives between kernels
__device__ float g_cA[NIMG * HS * WS];   // 25.2 MB

// ---------------------------------------------------------------------------
// Kernel 1: Haar DWT. cA -> g_cA, cH/cV -> d_out "high" region directly.
// (HBM-bound at roofline; unchanged.)
// ---------------------------------------------------------------------------
__global__ void dwt_kernel(const float* __restrict__ x, float* __restrict__ high) {
    int i   = blockIdx.x;
    int img = blockIdx.y;
    int t   = threadIdx.x;

    const float4* r0 = (const float4*)(x + ((size_t)img * HH + 2 * i) * WW);
    const float4* r1 = r0 + (WW / 4);
    float4 t0 = r0[t];
    float4 t1 = r1[t];

    float a0 = t0.x, b0 = t0.y, c0 = t1.x, d0 = t1.y;
    float a1 = t0.z, b1 = t0.w, c1 = t1.z, d1 = t1.w;

    float2 vA = make_float2(0.5f * (a0 + b0 + c0 + d0), 0.5f * (a1 + b1 + c1 + d1));
    float2 vH = make_float2(0.5f * (a0 + b0 - c0 - d0), 0.5f * (a1 + b1 - c1 - d1));
    float2 vV = make_float2(0.5f * (a0 - b0 + c0 - d0), 0.5f * (a1 - b1 + c1 - d1));

    size_t oA = (size_t)img * HS * WS + (size_t)i * WS + 2 * t;
    *(float2*)(g_cA + oA) = vA;

    size_t oH = (size_t)img * (2 * HS * WS) + (size_t)i * WS + 2 * t;
    *(float2*)(high + oH) = vH;
    *(float2*)(high + oH + HS * WS) = vV;
}

// ---------------------------------------------------------------------------
// conv1 pair stage: TWO output channels per pass, packed in f32x2 lanes.
// wq[k] = (w_ch0[k], w_ch1[k]); inputs broadcast pk(x,x). One patch read
// serves both channels: per task 8 LDS.64 + 16 packs + 36 fma2.
// Results written to two separate per-channel tiles (conv2 layout unchanged).
// ---------------------------------------------------------------------------
__device__ __forceinline__ void conv1_pair(
    const float (*cAt)[72], float (*d0)[36], float (*d1)[36],
    const ull* __restrict__ wqs, float2 bias2, int tid,
    int r0s, int c0s, bool interior)
{
    ull wq[9];
#pragma unroll
    for (int k = 0; k < 9; k++) wq[k] = wqs[k];

    int r = tid / 34, c = tid - 34 * r;
    for (int k = tid; k < 34 * 34; k += 256) {
        const float* base = &cAt[2 * r][2 * c];

        // a00=(conv 2r,2c), a01=(2r,2c+1), a10=(2r+1,2c), a11=(2r+1,2c+1),
        // each holding (ch0, ch1) in the two lanes.
        ull a00 = 0ull, a01 = 0ull, a10 = 0ull, a11 = 0ull;
#pragma unroll
        for (int i = 0; i < 4; i++) {          // input row 2r + i
            float2 q0 = *(const float2*)(base + i * 72);
            float2 q1 = *(const float2*)(base + i * 72 + 2);
            ull b0 = pk2(q0.x, q0.x);
            ull b1 = pk2(q0.y, q0.y);
            ull b2 = pk2(q1.x, q1.x);
            ull b3 = pk2(q1.y, q1.y);
            if (i < 3) {                        // ky = i contributes to dy=0
                fma2(a00, wq[3 * i + 0], b0);
                fma2(a00, wq[3 * i + 1], b1);
                fma2(a00, wq[3 * i + 2], b2);
                fma2(a01, wq[3 * i + 0], b1);
                fma2(a01, wq[3 * i + 1], b2);
                fma2(a01, wq[3 * i + 2], b3);
            }
            if (i > 0) {                        // ky = i-1 contributes to dy=1
                fma2(a10, wq[3 * (i - 1) + 0], b0);
                fma2(a10, wq[3 * (i - 1) + 1], b1);
                fma2(a10, wq[3 * (i - 1) + 2], b2);
                fma2(a11, wq[3 * (i - 1) + 0], b1);
                fma2(a11, wq[3 * (i - 1) + 1], b2);
                fma2(a11, wq[3 * (i - 1) + 2], b3);
            }
        }

        float l0, h0, l1, h1, l2, h2, l3, h3;
        upk2(a00, l0, h0); upk2(a01, l1, h1);
        upk2(a10, l2, h2); upk2(a11, l3, h3);
        float m0 = fmaxf(fmaxf(l0, l1), fmaxf(l2, l3));
        float m1 = fmaxf(fmaxf(h0, h1), fmaxf(h2, h3));
        m0 = fmaxf(m0 + bias2.x, 0.f);          // max(relu(x+b)) == relu(max+b)
        m1 = fmaxf(m1 + bias2.y, 0.f);
        if (!interior) {
            int rs = r0s + r, cs = c0s + c;
            if ((unsigned)rs >= 128u || (unsigned)cs >= 128u) { m0 = 0.f; m1 = 0.f; }
        }
        d0[r][c] = m0;
        d1[r][c] = m1;

        c += 18; r += 7;                        // advance 256 = 7*34 + 18
        if (c >= 34) { c -= 34; r++; }
    }
}

// ---------------------------------------------------------------------------
// conv2 stage: accumulate one input channel. Rolling 2-row broadcast buffer;
// oc-pairs in f32x2 lanes. (Unchanged from R8 best.)
// ---------------------------------------------------------------------------
__device__ __forceinline__ void conv2_stage(
    const float (*src)[36], const ull* __restrict__ wrow,
    int tx, int ty, ull acc[4][4])
{
    ull rA[4], rB[4];
    {
        float2 v0 = *(const float2*)&src[2 * ty][2 * tx];
        float2 v1 = *(const float2*)&src[2 * ty][2 * tx + 2];
        rA[0] = pk2(v0.x, v0.x); rA[1] = pk2(v0.y, v0.y);
        rA[2] = pk2(v1.x, v1.x); rA[3] = pk2(v1.y, v1.y);
    }
#pragma unroll
    for (int ky = 0; ky < 3; ky++) {
        ull* top = (ky & 1) ? rB : rA;
        ull* bot = (ky & 1) ? rA : rB;
        {
            float2 v0 = *(const float2*)&src[2 * ty + ky + 1][2 * tx];
            float2 v1 = *(const float2*)&src[2 * ty + ky + 1][2 * tx + 2];
            bot[0] = pk2(v0.x, v0.x); bot[1] = pk2(v0.y, v0.y);
            bot[2] = pk2(v1.x, v1.x); bot[3] = pk2(v1.y, v1.y);
        }
#pragma unroll
        for (int kx = 0; kx < 3; kx++) {
            ull w0 = wrow[(ky * 3 + kx) * 4 + 0];
            ull w1 = wrow[(ky * 3 + kx) * 4 + 1];
            ull w2 = wrow[(ky * 3 + kx) * 4 + 2];
            ull w3 = wrow[(ky * 3 + kx) * 4 + 3];
#pragma unroll
            for (int dx = 0; dx < 2; dx++) {
                ull pt = top[dx + kx];
                ull pb = bot[dx + kx];
                fma2(acc[dx][0], w0, pt);
                fma2(acc[dx][1], w1, pt);
                fma2(acc[dx][2], w2, pt);
                fma2(acc[dx][3], w3, pt);
                fma2(acc[2 + dx][0], w0, pb);
                fma2(acc[2 + dx][1], w1, pb);
                fma2(acc[2 + dx][2], w2, pb);
                fma2(acc[2 + dx][3], w3, pb);
            }
        }
    }
}

// ---------------------------------------------------------------------------
// Kernel 2: FUSED conv1+relu+pool -> conv2+relu+pool -> conv3(1x1).
// 4 s1 buffers per round (4 channels) -> 8 barriers total. 64-reg cap,
// 45.2 KB smem -> 4 CTAs/SM.
// ---------------------------------------------------------------------------
__global__ void __launch_bounds__(256, 4) fused_kernel(
    const float* __restrict__ w1, const float* __restrict__ b1,
    const float* __restrict__ w2, const float* __restrict__ b2,
    const float* __restrict__ w3, const float* __restrict__ b3,
    float* __restrict__ low)
{
    __shared__ __align__(16) float cAt[70][72];      // 20.2 KB
    __shared__ __align__(16) float s1t[4][34][36];   // 19.6 KB
    __shared__ ull    w2p[16 * 9 * 4];               //  4.6 KB
    __shared__ ull    w1p[8 * 9];                    //  576 B (ch-pair packed)
    __shared__ float2 b1p[8];
    __shared__ float  b2s[8];
    __shared__ float  w3s[32];
    __shared__ float  b3s[4];

    const int tx = threadIdx.x, ty = threadIdx.y;
    const int tid = ty * 16 + tx;
    const int px0 = blockIdx.x * 16, py0 = blockIdx.y * 16;  // pooled-64 origin
    const int img = blockIdx.z;

    // ---- weights to smem ----
    if (tid < 72) {
        int icp = tid / 9, k = tid - 9 * icp;
        w1p[tid] = pk2(w1[(2 * icp) * 9 + k], w1[(2 * icp + 1) * 9 + k]);
    }
    if (tid < 8)  b1p[tid] = make_float2(b1[2 * tid], b1[2 * tid + 1]);
    if (tid < 8)  b2s[tid] = b2[tid];
    if (tid < 32) w3s[tid] = w3[tid];
    if (tid < 4)  b3s[tid] = b3[tid];
    for (int idx = tid; idx < 16 * 9 * 4; idx += 256) {
        int ocp = idx & 3;
        int k   = (idx >> 2) % 9;
        int ic  = idx / 36;
        int oc0 = 2 * ocp;
        float lo = w2[(oc0 * 16 + ic) * 9 + k];
        float hi = w2[((oc0 + 1) * 16 + ic) * 9 + k];
        w2p[idx] = pk2(lo, hi);
    }

    // ---- cA tile: 70x70 at origin (4*py0-3, 4*px0-3), zero-padded ----
    {
        const float* in = g_cA + (size_t)img * HS * WS;
        const int gr0 = 4 * py0 - 3, gc0 = 4 * px0 - 3;
        int r = tid / 70, c = tid - 70 * r;
        for (int k = tid; k < 70 * 70; k += 256) {
            int ir = gr0 + r, ic = gc0 + c;
            float v = 0.f;
            if ((unsigned)ir < (unsigned)HS && (unsigned)ic < (unsigned)WS)
                v = in[(size_t)ir * WS + ic];
            cAt[r][c] = v;
            c += 46; r += 3;                 // advance 256 = 3*70 + 46
            if (c >= 70) { c -= 70; r++; }
        }
    }

    const int r0s = 2 * py0 - 1, c0s = 2 * px0 - 1;  // s1-tile global origin
    const bool interior = (py0 == 16 || py0 == 32) && (px0 == 16 || px0 == 32);

    ull acc[4][4];
#pragma unroll
    for (int q = 0; q < 4; q++)
#pragma unroll
        for (int p = 0; p < 4; p++) acc[q][p] = 0ull;

    for (int rnd = 0; rnd < 4; rnd++) {
        __syncthreads();   // s1t buffers free (covers init writes on rnd 0)
        conv1_pair((const float(*)[72])cAt, s1t[0], s1t[1],
                   &w1p[(2 * rnd) * 9],     b1p[2 * rnd],     tid, r0s, c0s, interior);
        conv1_pair((const float(*)[72])cAt, s1t[2], s1t[3],
                   &w1p[(2 * rnd + 1) * 9], b1p[2 * rnd + 1], tid, r0s, c0s, interior);
        __syncthreads();
#pragma unroll
        for (int j = 0; j < 4; j++)
            conv2_stage((const float(*)[36])s1t[j], &w2p[(4 * rnd + j) * 36], tx, ty, acc);
    }

    // ---- epilogue: bias + pool-max + relu, then 1x1 conv3 ----
    float r8[8];
#pragma unroll
    for (int p = 0; p < 4; p++) {
        float lo0, hi0, lo1, hi1, lo2, hi2, lo3, hi3;
        upk2(acc[0][p], lo0, hi0);
        upk2(acc[1][p], lo1, hi1);
        upk2(acc[2][p], lo2, hi2);
        upk2(acc[3][p], lo3, hi3);
        float mlo = fmaxf(fmaxf(lo0, lo1), fmaxf(lo2, lo3));
        float mhi = fmaxf(fmaxf(hi0, hi1), fmaxf(hi2, hi3));
        r8[2 * p]     = fmaxf(mlo + b2s[2 * p], 0.f);
        r8[2 * p + 1] = fmaxf(mhi + b2s[2 * p + 1], 0.f);
    }

    const int oy = py0 + ty, ox = px0 + tx;
    const int pix = oy * 64 + ox;
#pragma unroll
    for (int oc = 0; oc < 4; oc++) {
        float s = b3s[oc];
#pragma unroll
        for (int ic = 0; ic < 8; ic++) s = fmaf(w3s[oc * 8 + ic], r8[ic], s);
        low[((size_t)img * 4 + oc) * 4096 + pix] = s;
    }
}

// ---------------------------------------------------------------------------
extern "C" void kernel_launch(void* const* d_in, const int* in_sizes, int n_in,
                              void* d_out, int out_size) {
    const float* x  = (const float*)d_in[0];
    const float* w1 = (const float*)d_in[1];
    const float* b1 = (const float*)d_in[2];
    const float* w2 = (const float*)d_in[3];
    const float* b2 = (const float*)d_in[4];
    const float* w3 = (const float*)d_in[5];
    const float* b3 = (const float*)d_in[6];

    float* out  = (float*)d_out;
    float* low  = out;                    // 96*4*64*64 = 1,572,864 floats
    float* high = out + 1572864;          // 96*2*256*256 = 12,582,912 floats

    dwt_kernel<<<dim3(256, 96), 128>>>(x, high);
    fused_kernel<<<dim3(4, 4, NIMG), dim3(16, 16)>>>(w1, b1, w2, b2, w3, b3, low);
}

// round 10
// speedup vs baseline: 1.5542x; 1.0665x over previous
#include <cuda_runtime.h>

#define NIMG 96
#define HH 512
#define WW 512
#define HS 256   // cA resolution
#define WS 256

typedef unsigned long long ull;

__device__ __forceinline__ ull pk2(float lo, float hi) {
    ull r; asm("mov.b64 %0, {%1, %2};" : "=l"(r) : "f"(lo), "f"(hi)); return r;
}
__device__ __forceinline__ void upk2(ull v, float& lo, float& hi) {
    asm("mov.b64 {%0, %1}, %2;" : "=f"(lo), "=f"(hi) : "l"(v));
}
__device__ __forceinline__ void fma2(ull& d, ull a, ull b) {
    asm("fma.rn.f32x2 %0, %1, %2, %0;" : "+l"(d) : "l"(a), "l"(b));
}

// ---------------------------------------------------------------------------
// conv1 pair stage: TWO output channels per pass, packed in f32x2 lanes.
// wq[k] = (w_ch0[k], w_ch1[k]); inputs broadcast pk(x,x).
// t0 = rotated task start (load balance across the two calls per round).
// ---------------------------------------------------------------------------
__device__ __forceinline__ void conv1_pair(
    const float (*cAt)[72], float (*d0)[36], float (*d1)[36],
    const ull* __restrict__ wqs, float2 bias2, int t0,
    int r0s, int c0s, bool interior)
{
    ull wq[9];
    {   // wqs is 16B-aligned (stride-10 rows in w1p)
        ulonglong2 a = *(const ulonglong2*)(wqs);
        ulonglong2 b = *(const ulonglong2*)(wqs + 2);
        ulonglong2 c = *(const ulonglong2*)(wqs + 4);
        ulonglong2 d = *(const ulonglong2*)(wqs + 6);
        wq[0] = a.x; wq[1] = a.y; wq[2] = b.x; wq[3] = b.y;
        wq[4] = c.x; wq[5] = c.y; wq[6] = d.x; wq[7] = d.y;
        wq[8] = wqs[8];
    }

    int r = t0 / 34, c = t0 - 34 * r;
    for (int k = t0; k < 34 * 34; k += 256) {
        const float* base = &cAt[2 * r][2 * c];

        ull a00 = 0ull, a01 = 0ull, a10 = 0ull, a11 = 0ull;
#pragma unroll
        for (int i = 0; i < 4; i++) {          // input row 2r + i
            float2 q0 = *(const float2*)(base + i * 72);
            float2 q1 = *(const float2*)(base + i * 72 + 2);
            ull b0 = pk2(q0.x, q0.x);
            ull b1 = pk2(q0.y, q0.y);
            ull b2 = pk2(q1.x, q1.x);
            ull b3 = pk2(q1.y, q1.y);
            if (i < 3) {                        // ky = i contributes to dy=0
                fma2(a00, wq[3 * i + 0], b0);
                fma2(a00, wq[3 * i + 1], b1);
                fma2(a00, wq[3 * i + 2], b2);
                fma2(a01, wq[3 * i + 0], b1);
                fma2(a01, wq[3 * i + 1], b2);
                fma2(a01, wq[3 * i + 2], b3);
            }
            if (i > 0) {                        // ky = i-1 contributes to dy=1
                fma2(a10, wq[3 * (i - 1) + 0], b0);
                fma2(a10, wq[3 * (i - 1) + 1], b1);
                fma2(a10, wq[3 * (i - 1) + 2], b2);
                fma2(a11, wq[3 * (i - 1) + 0], b1);
                fma2(a11, wq[3 * (i - 1) + 1], b2);
                fma2(a11, wq[3 * (i - 1) + 2], b3);
            }
        }

        float l0, h0, l1, h1, l2, h2, l3, h3;
        upk2(a00, l0, h0); upk2(a01, l1, h1);
        upk2(a10, l2, h2); upk2(a11, l3, h3);
        float m0 = fmaxf(fmaxf(l0, l1), fmaxf(l2, l3));
        float m1 = fmaxf(fmaxf(h0, h1), fmaxf(h2, h3));
        m0 = fmaxf(m0 + bias2.x, 0.f);          // max(relu(x+b)) == relu(max+b)
        m1 = fmaxf(m1 + bias2.y, 0.f);
        if (!interior) {
            int rs = r0s + r, cs = c0s + c;
            if ((unsigned)rs >= 128u || (unsigned)cs >= 128u) { m0 = 0.f; m1 = 0.f; }
        }
        d0[r][c] = m0;
        d1[r][c] = m1;

        c += 18; r += 7;                        // advance 256 = 7*34 + 18
        if (c >= 34) { c -= 34; r++; }
    }
}

// ---------------------------------------------------------------------------
// conv2 stage: accumulate one input channel. Rolling 2-row broadcast buffer;
// oc-pairs in f32x2 lanes. Weights via LDS.128 (2x ulonglong2 per position).
// ---------------------------------------------------------------------------
__device__ __forceinline__ void conv2_stage(
    const float (*src)[36], const ull* __restrict__ wrow,
    int tx, int ty, ull acc[4][4])
{
    ull rA[4], rB[4];
    {
        float2 v0 = *(const float2*)&src[2 * ty][2 * tx];
        float2 v1 = *(const float2*)&src[2 * ty][2 * tx + 2];
        rA[0] = pk2(v0.x, v0.x); rA[1] = pk2(v0.y, v0.y);
        rA[2] = pk2(v1.x, v1.x); rA[3] = pk2(v1.y, v1.y);
    }
#pragma unroll
    for (int ky = 0; ky < 3; ky++) {
        ull* top = (ky & 1) ? rB : rA;
        ull* bot = (ky & 1) ? rA : rB;
        {
            float2 v0 = *(const float2*)&src[2 * ty + ky + 1][2 * tx];
            float2 v1 = *(const float2*)&src[2 * ty + ky + 1][2 * tx + 2];
            bot[0] = pk2(v0.x, v0.x); bot[1] = pk2(v0.y, v0.y);
            bot[2] = pk2(v1.x, v1.x); bot[3] = pk2(v1.y, v1.y);
        }
#pragma unroll
        for (int kx = 0; kx < 3; kx++) {
            ulonglong2 wa = *(const ulonglong2*)&wrow[(ky * 3 + kx) * 4];
            ulonglong2 wb = *(const ulonglong2*)&wrow[(ky * 3 + kx) * 4 + 2];
#pragma unroll
            for (int dx = 0; dx < 2; dx++) {
                ull pt = top[dx + kx];
                ull pb = bot[dx + kx];
                fma2(acc[dx][0], wa.x, pt);
                fma2(acc[dx][1], wa.y, pt);
                fma2(acc[dx][2], wb.x, pt);
                fma2(acc[dx][3], wb.y, pt);
                fma2(acc[2 + dx][0], wa.x, pb);
                fma2(acc[2 + dx][1], wa.y, pb);
                fma2(acc[2 + dx][2], wb.x, pb);
                fma2(acc[2 + dx][3], wb.y, pb);
            }
        }
    }
}

// ---------------------------------------------------------------------------
// SINGLE FUSED KERNEL: Haar DWT (cA tile in smem, cH/cV straight to d_out)
// -> conv1+relu+pool -> conv2+relu+pool -> conv3(1x1) -> "low" region.
// Each block owns a 64x64 cA region (16x16 pooled output tile); halo of 3.
// ---------------------------------------------------------------------------
__global__ void __launch_bounds__(256, 4) fused_kernel(
    const float* __restrict__ x,
    const float* __restrict__ w1, const float* __restrict__ b1,
    const float* __restrict__ w2, const float* __restrict__ b2,
    const float* __restrict__ w3, const float* __restrict__ b3,
    float* __restrict__ low, float* __restrict__ high)
{
    __shared__ __align__(16) float cAt[70][72];      // 20.2 KB
    __shared__ __align__(16) float s1t[4][34][36];   // 19.6 KB
    __shared__ __align__(16) ull    w2p[16 * 9 * 4]; //  4.6 KB
    __shared__ __align__(16) ull    w1p[8 * 10];     //  640 B (stride 10: 16B rows)
    __shared__ float2 b1p[8];
    __shared__ float  b2s[8];
    __shared__ float  w3s[32];
    __shared__ float  b3s[4];

    const int tx = threadIdx.x, ty = threadIdx.y;
    const int tid = ty * 16 + tx;
    const int px0 = blockIdx.x * 16, py0 = blockIdx.y * 16;  // pooled-64 origin
    const int img = blockIdx.z;

    // ---- weights to smem ----
    if (tid < 80) {
        int icp = tid / 10, k = tid - 10 * icp;
        w1p[tid] = (k < 9) ? pk2(w1[(2 * icp) * 9 + k], w1[(2 * icp + 1) * 9 + k]) : 0ull;
    }
    if (tid < 8)  b1p[tid] = make_float2(b1[2 * tid], b1[2 * tid + 1]);
    if (tid < 8)  b2s[tid] = b2[tid];
    if (tid < 32) w3s[tid] = w3[tid];
    if (tid < 4)  b3s[tid] = b3[tid];
    for (int idx = tid; idx < 16 * 9 * 4; idx += 256) {
        int ocp = idx & 3;
        int k   = (idx >> 2) % 9;
        int ic  = idx / 36;
        int oc0 = 2 * ocp;
        float lo = w2[(oc0 * 16 + ic) * 9 + k];
        float hi = w2[((oc0 + 1) * 16 + ic) * 9 + k];
        w2p[idx] = pk2(lo, hi);
    }

    // ---- DWT fill: cA 70x70 tile from x; cH/cV for owned 64x64 -> high ----
    {
        const float* xin = x + (size_t)img * HH * WW;
        float* highimg = high + (size_t)img * (2 * HS * WS);
        const int gr0 = 4 * py0 - 3, gc0 = 4 * px0 - 3;  // cA-space tile origin
        int r = tid / 70, c = tid - 70 * r;
        for (int k = tid; k < 70 * 70; k += 256) {
            int ir = gr0 + r, ic = gc0 + c;              // cA coords
            float va = 0.f, vh = 0.f, vv = 0.f;
            if ((unsigned)ir < (unsigned)HS && (unsigned)ic < (unsigned)WS) {
                const float* p0 = xin + (size_t)(2 * ir) * WW + 2 * ic;
                float2 q0 = *(const float2*)p0;
                float2 q1 = *(const float2*)(p0 + WW);
                float s0 = q0.x + q0.y, s1 = q1.x + q1.y;
                float e0 = q0.x - q0.y, e1 = q1.x - q1.y;
                va = 0.5f * (s0 + s1);
                vh = 0.5f * (s0 - s1);
                vv = 0.5f * (e0 + e1);
            }
            cAt[r][c] = va;
            if (r >= 3 && r < 67 && c >= 3 && c < 67) {  // owned region only
                highimg[(size_t)ir * WS + ic] = vh;
                highimg[(size_t)(HS * WS) + (size_t)ir * WS + ic] = vv;
            }
            c += 46; r += 3;                 // advance 256 = 3*70 + 46
            if (c >= 70) { c -= 70; r++; }
        }
    }

    const int r0s = 2 * py0 - 1, c0s = 2 * px0 - 1;  // s1-tile global origin
    const bool interior = (py0 == 16 || py0 == 32) && (px0 == 16 || px0 == 32);
    const int trot = (tid + 128) & 255;              // rotated start: balance

    ull acc[4][4];
#pragma unroll
    for (int q = 0; q < 4; q++)
#pragma unroll
        for (int p = 0; p < 4; p++) acc[q][p] = 0ull;

    for (int rnd = 0; rnd < 4; rnd++) {
        __syncthreads();   // s1t free; rnd 0 also covers fill + weight writes
        conv1_pair((const float(*)[72])cAt, s1t[0], s1t[1],
                   &w1p[(2 * rnd) * 10],     b1p[2 * rnd],     tid,  r0s, c0s, interior);
        conv1_pair((const float(*)[72])cAt, s1t[2], s1t[3],
                   &w1p[(2 * rnd + 1) * 10], b1p[2 * rnd + 1], trot, r0s, c0s, interior);
        __syncthreads();
#pragma unroll
        for (int j = 0; j < 4; j++)
            conv2_stage((const float(*)[36])s1t[j], &w2p[(4 * rnd + j) * 36], tx, ty, acc);
    }

    // ---- epilogue: bias + pool-max + relu, then 1x1 conv3 ----
    float r8[8];
#pragma unroll
    for (int p = 0; p < 4; p++) {
        float lo0, hi0, lo1, hi1, lo2, hi2, lo3, hi3;
        upk2(acc[0][p], lo0, hi0);
        upk2(acc[1][p], lo1, hi1);
        upk2(acc[2][p], lo2, hi2);
        upk2(acc[3][p], lo3, hi3);
        float mlo = fmaxf(fmaxf(lo0, lo1), fmaxf(lo2, lo3));
        float mhi = fmaxf(fmaxf(hi0, hi1), fmaxf(hi2, hi3));
        r8[2 * p]     = fmaxf(mlo + b2s[2 * p], 0.f);
        r8[2 * p + 1] = fmaxf(mhi + b2s[2 * p + 1], 0.f);
    }

    const int oy = py0 + ty, ox = px0 + tx;
    const int pix = oy * 64 + ox;
#pragma unroll
    for (int oc = 0; oc < 4; oc++) {
        float s = b3s[oc];
#pragma unroll
        for (int ic = 0; ic < 8; ic++) s = fmaf(w3s[oc * 8 + ic], r8[ic], s);
        low[((size_t)img * 4 + oc) * 4096 + pix] = s;
    }
}

// ---------------------------------------------------------------------------
extern "C" void kernel_launch(void* const* d_in, const int* in_sizes, int n_in,
                              void* d_out, int out_size) {
    const float* x  = (const float*)d_in[0];
    const float* w1 = (const float*)d_in[1];
    const float* b1 = (const float*)d_in[2];
    const float* w2 = (const float*)d_in[3];
    const float* b2 = (const float*)d_in[4];
    const float* w3 = (const float*)d_in[5];
    const float* b3 = (const float*)d_in[6];

    float* out  = (float*)d_out;
    float* low  = out;                    // 96*4*64*64 = 1,572,864 floats
    float* high = out + 1572864;          // 96*2*256*256 = 12,582,912 floats

    fused_kernel<<<dim3(4, 4, NIMG), dim3(16, 16)>>>(x, w1, b1, w2, b2, w3, b3, low, high);
}

// round 11
// speedup vs baseline: 1.5811x; 1.0173x over previous
#include <cuda_runtime.h>

#define NIMG 96
#define HH 512
#define WW 512
#define HS 256   // cA resolution
#define WS 256

typedef unsigned long long ull;

__device__ __forceinline__ ull pk2(float lo, float hi) {
    ull r; asm("mov.b64 %0, {%1, %2};" : "=l"(r) : "f"(lo), "f"(hi)); return r;
}
__device__ __forceinline__ void upk2(ull v, float& lo, float& hi) {
    asm("mov.b64 {%0, %1}, %2;" : "=f"(lo), "=f"(hi) : "l"(v));
}
__device__ __forceinline__ void fma2(ull& d, ull a, ull b) {
    asm("fma.rn.f32x2 %0, %1, %2, %0;" : "+l"(d) : "l"(a), "l"(b));
}

// ---------------------------------------------------------------------------
// conv1 pair stage: TWO output channels per pass, packed in f32x2 lanes.
// s1 tile is 18x34 (for the 16x8 pooled block tile). 612 tasks / 128 thr.
// ---------------------------------------------------------------------------
__device__ __forceinline__ void conv1_pair(
    const float (*cAt)[72], float (*d0)[36], float (*d1)[36],
    const ull* __restrict__ wqs, float2 bias2, int t0,
    int r0s, int c0s, bool interior)
{
    ull wq[9];
    {   // wqs is 16B-aligned (stride-10 rows in w1p)
        ulonglong2 a = *(const ulonglong2*)(wqs);
        ulonglong2 b = *(const ulonglong2*)(wqs + 2);
        ulonglong2 c = *(const ulonglong2*)(wqs + 4);
        ulonglong2 d = *(const ulonglong2*)(wqs + 6);
        wq[0] = a.x; wq[1] = a.y; wq[2] = b.x; wq[3] = b.y;
        wq[4] = c.x; wq[5] = c.y; wq[6] = d.x; wq[7] = d.y;
        wq[8] = wqs[8];
    }

    int r = t0 / 34, c = t0 - 34 * r;
    for (int k = t0; k < 18 * 34; k += 128) {
        const float* base = &cAt[2 * r][2 * c];

        ull a00 = 0ull, a01 = 0ull, a10 = 0ull, a11 = 0ull;
#pragma unroll
        for (int i = 0; i < 4; i++) {          // input row 2r + i
            float2 q0 = *(const float2*)(base + i * 72);
            float2 q1 = *(const float2*)(base + i * 72 + 2);
            ull b0 = pk2(q0.x, q0.x);
            ull b1 = pk2(q0.y, q0.y);
            ull b2 = pk2(q1.x, q1.x);
            ull b3 = pk2(q1.y, q1.y);
            if (i < 3) {                        // ky = i contributes to dy=0
                fma2(a00, wq[3 * i + 0], b0);
                fma2(a00, wq[3 * i + 1], b1);
                fma2(a00, wq[3 * i + 2], b2);
                fma2(a01, wq[3 * i + 0], b1);
                fma2(a01, wq[3 * i + 1], b2);
                fma2(a01, wq[3 * i + 2], b3);
            }
            if (i > 0) {                        // ky = i-1 contributes to dy=1
                fma2(a10, wq[3 * (i - 1) + 0], b0);
                fma2(a10, wq[3 * (i - 1) + 1], b1);
                fma2(a10, wq[3 * (i - 1) + 2], b2);
                fma2(a11, wq[3 * (i - 1) + 0], b1);
                fma2(a11, wq[3 * (i - 1) + 1], b2);
                fma2(a11, wq[3 * (i - 1) + 2], b3);
            }
        }

        float l0, h0, l1, h1, l2, h2, l3, h3;
        upk2(a00, l0, h0); upk2(a01, l1, h1);
        upk2(a10, l2, h2); upk2(a11, l3, h3);
        float m0 = fmaxf(fmaxf(l0, l1), fmaxf(l2, l3));
        float m1 = fmaxf(fmaxf(h0, h1), fmaxf(h2, h3));
        m0 = fmaxf(m0 + bias2.x, 0.f);          // max(relu(x+b)) == relu(max+b)
        m1 = fmaxf(m1 + bias2.y, 0.f);
        if (!interior) {
            int rs = r0s + r, cs = c0s + c;
            if ((unsigned)rs >= 128u || (unsigned)cs >= 128u) { m0 = 0.f; m1 = 0.f; }
        }
        d0[r][c] = m0;
        d1[r][c] = m1;

        c += 26; r += 3;                        // advance 128 = 3*34 + 26
        if (c >= 34) { c -= 34; r++; }
    }
}

// ---------------------------------------------------------------------------
// conv2 stage: accumulate one input channel. Rolling 2-row broadcast buffer;
// oc-pairs in f32x2 lanes. Weights via LDS.128.
// ---------------------------------------------------------------------------
__device__ __forceinline__ void conv2_stage(
    const float (*src)[36], const ull* __restrict__ wrow,
    int tx, int ty, ull acc[4][4])
{
    ull rA[4], rB[4];
    {
        float2 v0 = *(const float2*)&src[2 * ty][2 * tx];
        float2 v1 = *(const float2*)&src[2 * ty][2 * tx + 2];
        rA[0] = pk2(v0.x, v0.x); rA[1] = pk2(v0.y, v0.y);
        rA[2] = pk2(v1.x, v1.x); rA[3] = pk2(v1.y, v1.y);
    }
#pragma unroll
    for (int ky = 0; ky < 3; ky++) {
        ull* top = (ky & 1) ? rB : rA;
        ull* bot = (ky & 1) ? rA : rB;
        {
            float2 v0 = *(const float2*)&src[2 * ty + ky + 1][2 * tx];
            float2 v1 = *(const float2*)&src[2 * ty + ky + 1][2 * tx + 2];
            bot[0] = pk2(v0.x, v0.x); bot[1] = pk2(v0.y, v0.y);
            bot[2] = pk2(v1.x, v1.x); bot[3] = pk2(v1.y, v1.y);
        }
#pragma unroll
        for (int kx = 0; kx < 3; kx++) {
            ulonglong2 wa = *(const ulonglong2*)&wrow[(ky * 3 + kx) * 4];
            ulonglong2 wb = *(const ulonglong2*)&wrow[(ky * 3 + kx) * 4 + 2];
#pragma unroll
            for (int dx = 0; dx < 2; dx++) {
                ull pt = top[dx + kx];
                ull pb = bot[dx + kx];
                fma2(acc[dx][0], wa.x, pt);
                fma2(acc[dx][1], wa.y, pt);
                fma2(acc[dx][2], wb.x, pt);
                fma2(acc[dx][3], wb.y, pt);
                fma2(acc[2 + dx][0], wa.x, pb);
                fma2(acc[2 + dx][1], wa.y, pb);
                fma2(acc[2 + dx][2], wb.x, pb);
                fma2(acc[2 + dx][3], wb.y, pb);
            }
        }
    }
}

// ---------------------------------------------------------------------------
// SINGLE FUSED KERNEL, 128-thread blocks (16x8 pooled tile), 8 CTAs/SM.
// Haar DWT (cA tile in smem, cH/cV -> d_out) -> conv1+relu+pool ->
// conv2+relu+pool -> conv3(1x1) -> "low".
// Each block owns a 64x32 cA region; halo 3. grid (4, 8, 96).
// ---------------------------------------------------------------------------
__global__ void __launch_bounds__(128, 8) fused_kernel(
    const float* __restrict__ x,
    const float* __restrict__ w1, const float* __restrict__ b1,
    const float* __restrict__ w2, const float* __restrict__ b2,
    const float* __restrict__ w3, const float* __restrict__ b3,
    float* __restrict__ low, float* __restrict__ high)
{
    __shared__ __align__(16) float cAt[38][72];      // 10.9 KB
    __shared__ __align__(16) float s1t[4][18][36];   // 10.4 KB
    __shared__ __align__(16) ull    w2p[16 * 9 * 4]; //  4.6 KB
    __shared__ __align__(16) ull    w1p[8 * 10];     //  640 B (stride 10: 16B rows)
    __shared__ float2 b1p[8];
    __shared__ float  b2s[8];
    __shared__ float  w3s[32];
    __shared__ float  b3s[4];

    const int tx = threadIdx.x, ty = threadIdx.y;    // block (16, 8)
    const int tid = ty * 16 + tx;
    const int px0 = blockIdx.x * 16;                 // pooled-64 col origin
    const int py0 = blockIdx.y * 8;                  // pooled-64 row origin
    const int img = blockIdx.z;

    // ---- weights to smem ----
    if (tid < 80) {
        int icp = tid / 10, k = tid - 10 * icp;
        w1p[tid] = (k < 9) ? pk2(w1[(2 * icp) * 9 + k], w1[(2 * icp + 1) * 9 + k]) : 0ull;
    }
    if (tid < 8)  b1p[tid] = make_float2(b1[2 * tid], b1[2 * tid + 1]);
    if (tid < 8)  b2s[tid] = b2[tid];
    if (tid < 32) w3s[tid] = w3[tid];
    if (tid < 4)  b3s[tid] = b3[tid];
    for (int idx = tid; idx < 16 * 9 * 4; idx += 128) {
        int ocp = idx & 3;
        int k   = (idx >> 2) % 9;
        int ic  = idx / 36;
        int oc0 = 2 * ocp;
        float lo = w2[(oc0 * 16 + ic) * 9 + k];
        float hi = w2[((oc0 + 1) * 16 + ic) * 9 + k];
        w2p[idx] = pk2(lo, hi);
    }

    // ---- DWT fill: cA 38x70 tile from x; cH/cV for owned 64x32 -> high ----
    {
        const float* xin = x + (size_t)img * HH * WW;
        float* highimg = high + (size_t)img * (2 * HS * WS);
        const int gr0 = 4 * py0 - 3, gc0 = 4 * px0 - 3;  // cA-space tile origin
        int r = tid / 70, c = tid - 70 * r;
        for (int k = tid; k < 38 * 70; k += 128) {
            int ir = gr0 + r, ic = gc0 + c;              // cA coords
            float va = 0.f, vh = 0.f, vv = 0.f;
            if ((unsigned)ir < (unsigned)HS && (unsigned)ic < (unsigned)WS) {
                const float* p0 = xin + (size_t)(2 * ir) * WW + 2 * ic;
                float2 q0 = *(const float2*)p0;
                float2 q1 = *(const float2*)(p0 + WW);
                float s0 = q0.x + q0.y, s1 = q1.x + q1.y;
                float e0 = q0.x - q0.y, e1 = q1.x - q1.y;
                va = 0.5f * (s0 + s1);
                vh = 0.5f * (s0 - s1);
                vv = 0.5f * (e0 + e1);
            }
            cAt[r][c] = va;
            if (r >= 3 && r < 35 && c >= 3 && c < 67) {  // owned region only
                highimg[(size_t)ir * WS + ic] = vh;
                highimg[(size_t)(HS * WS) + (size_t)ir * WS + ic] = vv;
            }
            c += 58; r += 1;                 // advance 128 = 1*70 + 58
            if (c >= 70) { c -= 70; r++; }
        }
    }

    const int r0s = 2 * py0 - 1, c0s = 2 * px0 - 1;  // s1-tile global origin
    const bool interior = (py0 >= 8 && py0 <= 48) && (px0 == 16 || px0 == 32);
    const int trot = (tid + 100) & 127;              // rotated start: balance

    ull acc[4][4];
#pragma unroll
    for (int q = 0; q < 4; q++)
#pragma unroll
        for (int p = 0; p < 4; p++) acc[q][p] = 0ull;

    for (int rnd = 0; rnd < 4; rnd++) {
        __syncthreads();   // s1t free; rnd 0 also covers fill + weight writes
        conv1_pair((const float(*)[72])cAt, s1t[0], s1t[1],
                   &w1p[(2 * rnd) * 10],     b1p[2 * rnd],     tid,  r0s, c0s, interior);
        conv1_pair((const float(*)[72])cAt, s1t[2], s1t[3],
                   &w1p[(2 * rnd + 1) * 10], b1p[2 * rnd + 1], trot, r0s, c0s, interior);
        __syncthreads();
#pragma unroll
        for (int j = 0; j < 4; j++)
            conv2_stage((const float(*)[36])s1t[j], &w2p[(4 * rnd + j) * 36], tx, ty, acc);
    }

    // ---- epilogue: bias + pool-max + relu, then 1x1 conv3 ----
    float r8[8];
#pragma unroll
    for (int p = 0; p < 4; p++) {
        float lo0, hi0, lo1, hi1, lo2, hi2, lo3, hi3;
        upk2(acc[0][p], lo0, hi0);
        upk2(acc[1][p], lo1, hi1);
        upk2(acc[2][p], lo2, hi2);
        upk2(acc[3][p], lo3, hi3);
        float mlo = fmaxf(fmaxf(lo0, lo1), fmaxf(lo2, lo3));
        float mhi = fmaxf(fmaxf(hi0, hi1), fmaxf(hi2, hi3));
        r8[2 * p]     = fmaxf(mlo + b2s[2 * p], 0.f);
        r8[2 * p + 1] = fmaxf(mhi + b2s[2 * p + 1], 0.f);
    }

    const int oy = py0 + ty, ox = px0 + tx;
    const int pix = oy * 64 + ox;
#pragma unroll
    for (int oc = 0; oc < 4; oc++) {
        float s = b3s[oc];
#pragma unroll
        for (int ic = 0; ic < 8; ic++) s = fmaf(w3s[oc * 8 + ic], r8[ic], s);
        low[((size_t)img * 4 + oc) * 4096 + pix] = s;
    }
}

// ---------------------------------------------------------------------------
extern "C" void kernel_launch(void* const* d_in, const int* in_sizes, int n_in,
                              void* d_out, int out_size) {
    const float* x  = (const float*)d_in[0];
    const float* w1 = (const float*)d_in[1];
    const float* b1 = (const float*)d_in[2];
    const float* w2 = (const float*)d_in[3];
    const float* b2 = (const float*)d_in[4];
    const float* w3 = (const float*)d_in[5];
    const float* b3 = (const float*)d_in[6];

    float* out  = (float*)d_out;
    float* low  = out;                    // 96*4*64*64 = 1,572,864 floats
    float* high = out + 1572864;          // 96*2*256*256 = 12,582,912 floats

    fused_kernel<<<dim3(4, 8, NIMG), dim3(16, 8)>>>(x, w1, b1, w2, b2, w3, b3, low, high);
}

// round 12
// speedup vs baseline: 1.7177x; 1.0864x over previous
#include <cuda_runtime.h>

#define NIMG 96
#define HH 512
#define WW 512
#define HS 256   // cA resolution
#define WS 256

typedef unsigned long long ull;

__device__ __forceinline__ ull pk2(float lo, float hi) {
    ull r; asm("mov.b64 %0, {%1, %2};" : "=l"(r) : "f"(lo), "f"(hi)); return r;
}
__device__ __forceinline__ void upk2(ull v, float& lo, float& hi) {
    asm("mov.b64 {%0, %1}, %2;" : "=f"(lo), "=f"(hi) : "l"(v));
}
__device__ __forceinline__ void fma2(ull& d, ull a, ull b) {
    asm("fma.rn.f32x2 %0, %1, %2, %0;" : "+l"(d) : "l"(a), "l"(b));
}

// ---------------------------------------------------------------------------
// conv1 pair stage, 2-WIDE: each task computes TWO adjacent pooled outputs
// (s1 cols 2cp, 2cp+1) for TWO output channels (f32x2 lanes) from a 4x6
// input strip. Task grid: 18 rows x 17 col-pairs = 306 tasks / 128 threads.
// Per task: 4x(LDS.128+LDS.64) + 24 packs + 72 fma2 -> 2 outputs x 2 ch.
// ---------------------------------------------------------------------------
__device__ __forceinline__ void conv1_pair(
    const float (*cAt)[72], float (*d0)[36], float (*d1)[36],
    const ull* __restrict__ wqs, float2 bias2, int t0,
    int r0s, int c0s, bool interior)
{
    ull wq[9];
    {   // wqs is 16B-aligned (stride-10 rows in w1p)
        ulonglong2 a = *(const ulonglong2*)(wqs);
        ulonglong2 b = *(const ulonglong2*)(wqs + 2);
        ulonglong2 c = *(const ulonglong2*)(wqs + 4);
        ulonglong2 d = *(const ulonglong2*)(wqs + 6);
        wq[0] = a.x; wq[1] = a.y; wq[2] = b.x; wq[3] = b.y;
        wq[4] = c.x; wq[5] = c.y; wq[6] = d.x; wq[7] = d.y;
        wq[8] = wqs[8];
    }

    int r = t0 / 17, cp = t0 - 17 * r;
    for (int k = t0; k < 18 * 17; k += 128) {
        const float* base = &cAt[2 * r][4 * cp];   // 16B aligned (16*cp bytes)

        // a[j][dy*2+dx]: output j in {0,1}, conv position (dy,dx);
        // lanes hold (ch0, ch1).
        ull a[2][4];
#pragma unroll
        for (int j = 0; j < 2; j++)
#pragma unroll
            for (int q = 0; q < 4; q++) a[j][q] = 0ull;

#pragma unroll
        for (int i = 0; i < 4; i++) {              // input row 2r + i
            float4 q0 = *(const float4*)(base + i * 72);
            float2 q1 = *(const float2*)(base + i * 72 + 4);
            ull bb[6];
            bb[0] = pk2(q0.x, q0.x); bb[1] = pk2(q0.y, q0.y);
            bb[2] = pk2(q0.z, q0.z); bb[3] = pk2(q0.w, q0.w);
            bb[4] = pk2(q1.x, q1.x); bb[5] = pk2(q1.y, q1.y);
            if (i < 3) {                            // ky = i -> dy = 0
#pragma unroll
                for (int kx = 0; kx < 3; kx++) {
                    ull w = wq[3 * i + kx];
                    fma2(a[0][0], w, bb[kx]);       // j=0, dx=0
                    fma2(a[0][1], w, bb[kx + 1]);   // j=0, dx=1
                    fma2(a[1][0], w, bb[kx + 2]);   // j=1, dx=0
                    fma2(a[1][1], w, bb[kx + 3]);   // j=1, dx=1
                }
            }
            if (i > 0) {                            // ky = i-1 -> dy = 1
#pragma unroll
                for (int kx = 0; kx < 3; kx++) {
                    ull w = wq[3 * (i - 1) + kx];
                    fma2(a[0][2], w, bb[kx]);
                    fma2(a[0][3], w, bb[kx + 1]);
                    fma2(a[1][2], w, bb[kx + 2]);
                    fma2(a[1][3], w, bb[kx + 3]);
                }
            }
        }

        float2 o0, o1;   // (col j=0, j=1) for ch0 / ch1
#pragma unroll
        for (int j = 0; j < 2; j++) {
            float l0, h0, l1, h1, l2, h2, l3, h3;
            upk2(a[j][0], l0, h0); upk2(a[j][1], l1, h1);
            upk2(a[j][2], l2, h2); upk2(a[j][3], l3, h3);
            float m0 = fmaxf(fmaxf(l0, l1), fmaxf(l2, l3));
            float m1 = fmaxf(fmaxf(h0, h1), fmaxf(h2, h3));
            m0 = fmaxf(m0 + bias2.x, 0.f);   // max(relu(x+b)) == relu(max+b)
            m1 = fmaxf(m1 + bias2.y, 0.f);
            if (!interior) {
                int rs = r0s + r, cs = c0s + 2 * cp + j;
                if ((unsigned)rs >= 128u || (unsigned)cs >= 128u) { m0 = 0.f; m1 = 0.f; }
            }
            ((float*)&o0)[j] = m0;
            ((float*)&o1)[j] = m1;
        }
        *(float2*)&d0[r][2 * cp] = o0;   // 8B aligned
        *(float2*)&d1[r][2 * cp] = o1;

        cp += 9; r += 7;                 // advance 128 = 7*17 + 9
        if (cp >= 17) { cp -= 17; r++; }
    }
}

// ---------------------------------------------------------------------------
// conv2 stage: accumulate one input channel. Rolling 2-row broadcast buffer;
// oc-pairs in f32x2 lanes. Weights via LDS.128. (Unchanged — wavefront audit
// shows this form is already near-optimal.)
// ---------------------------------------------------------------------------
__device__ __forceinline__ void conv2_stage(
    const float (*src)[36], const ull* __restrict__ wrow,
    int tx, int ty, ull acc[4][4])
{
    ull rA[4], rB[4];
    {
        float2 v0 = *(const float2*)&src[2 * ty][2 * tx];
        float2 v1 = *(const float2*)&src[2 * ty][2 * tx + 2];
        rA[0] = pk2(v0.x, v0.x); rA[1] = pk2(v0.y, v0.y);
        rA[2] = pk2(v1.x, v1.x); rA[3] = pk2(v1.y, v1.y);
    }
#pragma unroll
    for (int ky = 0; ky < 3; ky++) {
        ull* top = (ky & 1) ? rB : rA;
        ull* bot = (ky & 1) ? rA : rB;
        {
            float2 v0 = *(const float2*)&src[2 * ty + ky + 1][2 * tx];
            float2 v1 = *(const float2*)&src[2 * ty + ky + 1][2 * tx + 2];
            bot[0] = pk2(v0.x, v0.x); bot[1] = pk2(v0.y, v0.y);
            bot[2] = pk2(v1.x, v1.x); bot[3] = pk2(v1.y, v1.y);
        }
#pragma unroll
        for (int kx = 0; kx < 3; kx++) {
            ulonglong2 wa = *(const ulonglong2*)&wrow[(ky * 3 + kx) * 4];
            ulonglong2 wb = *(const ulonglong2*)&wrow[(ky * 3 + kx) * 4 + 2];
#pragma unroll
            for (int dx = 0; dx < 2; dx++) {
                ull pt = top[dx + kx];
                ull pb = bot[dx + kx];
                fma2(acc[dx][0], wa.x, pt);
                fma2(acc[dx][1], wa.y, pt);
                fma2(acc[dx][2], wb.x, pt);
                fma2(acc[dx][3], wb.y, pt);
                fma2(acc[2 + dx][0], wa.x, pb);
                fma2(acc[2 + dx][1], wa.y, pb);
                fma2(acc[2 + dx][2], wb.x, pb);
                fma2(acc[2 + dx][3], wb.y, pb);
            }
        }
    }
}

// ---------------------------------------------------------------------------
// SINGLE FUSED KERNEL, 128-thread blocks (16x8 pooled tile), 8 CTAs/SM.
// Haar DWT (cA tile in smem, cH/cV -> d_out) -> conv1+relu+pool ->
// conv2+relu+pool -> conv3(1x1) -> "low". grid (4, 8, 96).
// ---------------------------------------------------------------------------
__global__ void __launch_bounds__(128, 8) fused_kernel(
    const float* __restrict__ x,
    const float* __restrict__ w1, const float* __restrict__ b1,
    const float* __restrict__ w2, const float* __restrict__ b2,
    const float* __restrict__ w3, const float* __restrict__ b3,
    float* __restrict__ low, float* __restrict__ high)
{
    __shared__ __align__(16) float cAt[38][72];      // 10.9 KB
    __shared__ __align__(16) float s1t[4][18][36];   // 10.4 KB
    __shared__ __align__(16) ull    w2p[16 * 9 * 4]; //  4.6 KB
    __shared__ __align__(16) ull    w1p[8 * 10];     //  640 B (stride 10: 16B rows)
    __shared__ float2 b1p[8];
    __shared__ float  b2s[8];
    __shared__ float  w3s[32];
    __shared__ float  b3s[4];

    const int tx = threadIdx.x, ty = threadIdx.y;    // block (16, 8)
    const int tid = ty * 16 + tx;
    const int px0 = blockIdx.x * 16;                 // pooled-64 col origin
    const int py0 = blockIdx.y * 8;                  // pooled-64 row origin
    const int img = blockIdx.z;

    // ---- weights to smem ----
    if (tid < 80) {
        int icp = tid / 10, k = tid - 10 * icp;
        w1p[tid] = (k < 9) ? pk2(w1[(2 * icp) * 9 + k], w1[(2 * icp + 1) * 9 + k]) : 0ull;
    }
    if (tid < 8)  b1p[tid] = make_float2(b1[2 * tid], b1[2 * tid + 1]);
    if (tid < 8)  b2s[tid] = b2[tid];
    if (tid < 32) w3s[tid] = w3[tid];
    if (tid < 4)  b3s[tid] = b3[tid];
    for (int idx = tid; idx < 16 * 9 * 4; idx += 128) {
        int ocp = idx & 3;
        int k   = (idx >> 2) % 9;
        int ic  = idx / 36;
        int oc0 = 2 * ocp;
        float lo = w2[(oc0 * 16 + ic) * 9 + k];
        float hi = w2[((oc0 + 1) * 16 + ic) * 9 + k];
        w2p[idx] = pk2(lo, hi);
    }

    // ---- DWT fill: cA 38x70 tile from x; cH/cV for owned 64x32 -> high ----
    {
        const float* xin = x + (size_t)img * HH * WW;
        float* highimg = high + (size_t)img * (2 * HS * WS);
        const int gr0 = 4 * py0 - 3, gc0 = 4 * px0 - 3;  // cA-space tile origin
        int r = tid / 70, c = tid - 70 * r;
        for (int k = tid; k < 38 * 70; k += 128) {
            int ir = gr0 + r, ic = gc0 + c;              // cA coords
            float va = 0.f, vh = 0.f, vv = 0.f;
            if ((unsigned)ir < (unsigned)HS && (unsigned)ic < (unsigned)WS) {
                const float* p0 = xin + (size_t)(2 * ir) * WW + 2 * ic;
                float2 q0 = *(const float2*)p0;
                float2 q1 = *(const float2*)(p0 + WW);
                float s0 = q0.x + q0.y, s1 = q1.x + q1.y;
                float e0 = q0.x - q0.y, e1 = q1.x - q1.y;
                va = 0.5f * (s0 + s1);
                vh = 0.5f * (s0 - s1);
                vv = 0.5f * (e0 + e1);
            }
            cAt[r][c] = va;
            if (r >= 3 && r < 35 && c >= 3 && c < 67) {  // owned region only
                highimg[(size_t)ir * WS + ic] = vh;
                highimg[(size_t)(HS * WS) + (size_t)ir * WS + ic] = vv;
            }
            c += 58; r += 1;                 // advance 128 = 1*70 + 58
            if (c >= 70) { c -= 70; r++; }
        }
    }

    const int r0s = 2 * py0 - 1, c0s = 2 * px0 - 1;  // s1-tile global origin
    const bool interior = (py0 >= 8 && py0 <= 48) && (px0 == 16 || px0 == 32);

    ull acc[4][4];
#pragma unroll
    for (int q = 0; q < 4; q++)
#pragma unroll
        for (int p = 0; p < 4; p++) acc[q][p] = 0ull;

    for (int rnd = 0; rnd < 4; rnd++) {
        __syncthreads();   // s1t free; rnd 0 also covers fill + weight writes
        const int tA = (tid + rnd * 32) & 127;            // rotate task starts
        const int tB = (tid + rnd * 32 + 64) & 127;       // per round: balance
        conv1_pair((const float(*)[72])cAt, s1t[0], s1t[1],
                   &w1p[(2 * rnd) * 10],     b1p[2 * rnd],     tA, r0s, c0s, interior);
        conv1_pair((const float(*)[72])cAt, s1t[2], s1t[3],
                   &w1p[(2 * rnd + 1) * 10], b1p[2 * rnd + 1], tB, r0s, c0s, interior);
        __syncthreads();
#pragma unroll
        for (int j = 0; j < 4; j++)
            conv2_stage((const float(*)[36])s1t[j], &w2p[(4 * rnd + j) * 36], tx, ty, acc);
    }

    // ---- epilogue: bias + pool-max + relu, then 1x1 conv3 ----
    float r8[8];
#pragma unroll
    for (int p = 0; p < 4; p++) {
        float lo0, hi0, lo1, hi1, lo2, hi2, lo3, hi3;
        upk2(acc[0][p], lo0, hi0);
        upk2(acc[1][p], lo1, hi1);
        upk2(acc[2][p], lo2, hi2);
        upk2(acc[3][p], lo3, hi3);
        float mlo = fmaxf(fmaxf(lo0, lo1), fmaxf(lo2, lo3));
        float mhi = fmaxf(fmaxf(hi0, hi1), fmaxf(hi2, hi3));
        r8[2 * p]     = fmaxf(mlo + b2s[2 * p], 0.f);
        r8[2 * p + 1] = fmaxf(mhi + b2s[2 * p + 1], 0.f);
    }

    const int oy = py0 + ty, ox = px0 + tx;
    const int pix = oy * 64 + ox;
#pragma unroll
    for (int oc = 0; oc < 4; oc++) {
        float s = b3s[oc];
#pragma unroll
        for (int ic = 0; ic < 8; ic++) s = fmaf(w3s[oc * 8 + ic], r8[ic], s);
        low[((size_t)img * 4 + oc) * 4096 + pix] = s;
    }
}

// ---------------------------------------------------------------------------
extern "C" void kernel_launch(void* const* d_in, const int* in_sizes, int n_in,
                              void* d_out, int out_size) {
    const float* x  = (const float*)d_in[0];
    const float* w1 = (const float*)d_in[1];
    const float* b1 = (const float*)d_in[2];
    const float* w2 = (const float*)d_in[3];
    const float* b2 = (const float*)d_in[4];
    const float* w3 = (const float*)d_in[5];
    const float* b3 = (const float*)d_in[6];

    float* out  = (float*)d_out;
    float* low  = out;                    // 96*4*64*64 = 1,572,864 floats
    float* high = out + 1572864;          // 96*2*256*256 = 12,582,912 floats

    fused_kernel<<<dim3(4, 8, NIMG), dim3(16, 8)>>>(x, w1, b1, w2, b2, w3, b3, low, high);
}

// round 13
// speedup vs baseline: 1.7182x; 1.0002x over previous
#include <cuda_runtime.h>

#define NIMG 96
#define HH 512
#define WW 512
#define HS 256   // cA resolution
#define WS 256

#define NCTA 1184          // 148 SMs x 8 resident CTAs
#define NTILES (NIMG * 32) // 4 x 8 tiles per image

typedef unsigned long long ull;

__device__ __forceinline__ ull pk2(float lo, float hi) {
    ull r; asm("mov.b64 %0, {%1, %2};" : "=l"(r) : "f"(lo), "f"(hi)); return r;
}
__device__ __forceinline__ void upk2(ull v, float& lo, float& hi) {
    asm("mov.b64 {%0, %1}, %2;" : "=f"(lo), "=f"(hi) : "l"(v));
}
__device__ __forceinline__ void fma2(ull& d, ull a, ull b) {
    asm("fma.rn.f32x2 %0, %1, %2, %0;" : "+l"(d) : "l"(a), "l"(b));
}

// ---------------------------------------------------------------------------
// conv1 pair stage, 2-WIDE: two adjacent pooled outputs x two channels
// (f32x2 lanes) per task from a 4x6 strip. 18x17 task grid / 128 threads.
// ---------------------------------------------------------------------------
__device__ __forceinline__ void conv1_pair(
    const float (*cAt)[72], float (*d0)[36], float (*d1)[36],
    const ull* __restrict__ wqs, float2 bias2, int t0,
    int r0s, int c0s, bool interior)
{
    ull wq[9];
    {   // wqs is 16B-aligned (stride-10 rows in w1p)
        ulonglong2 a = *(const ulonglong2*)(wqs);
        ulonglong2 b = *(const ulonglong2*)(wqs + 2);
        ulonglong2 c = *(const ulonglong2*)(wqs + 4);
        ulonglong2 d = *(const ulonglong2*)(wqs + 6);
        wq[0] = a.x; wq[1] = a.y; wq[2] = b.x; wq[3] = b.y;
        wq[4] = c.x; wq[5] = c.y; wq[6] = d.x; wq[7] = d.y;
        wq[8] = wqs[8];
    }

    int r = t0 / 17, cp = t0 - 17 * r;
    for (int k = t0; k < 18 * 17; k += 128) {
        const float* base = &cAt[2 * r][4 * cp];   // 16B aligned

        ull a[2][4];
#pragma unroll
        for (int j = 0; j < 2; j++)
#pragma unroll
            for (int q = 0; q < 4; q++) a[j][q] = 0ull;

#pragma unroll
        for (int i = 0; i < 4; i++) {              // input row 2r + i
            float4 q0 = *(const float4*)(base + i * 72);
            float2 q1 = *(const float2*)(base + i * 72 + 4);
            ull bb[6];
            bb[0] = pk2(q0.x, q0.x); bb[1] = pk2(q0.y, q0.y);
            bb[2] = pk2(q0.z, q0.z); bb[3] = pk2(q0.w, q0.w);
            bb[4] = pk2(q1.x, q1.x); bb[5] = pk2(q1.y, q1.y);
            if (i < 3) {                            // ky = i -> dy = 0
#pragma unroll
                for (int kx = 0; kx < 3; kx++) {
                    ull w = wq[3 * i + kx];
                    fma2(a[0][0], w, bb[kx]);
                    fma2(a[0][1], w, bb[kx + 1]);
                    fma2(a[1][0], w, bb[kx + 2]);
                    fma2(a[1][1], w, bb[kx + 3]);
                }
            }
            if (i > 0) {                            // ky = i-1 -> dy = 1
#pragma unroll
                for (int kx = 0; kx < 3; kx++) {
                    ull w = wq[3 * (i - 1) + kx];
                    fma2(a[0][2], w, bb[kx]);
                    fma2(a[0][3], w, bb[kx + 1]);
                    fma2(a[1][2], w, bb[kx + 2]);
                    fma2(a[1][3], w, bb[kx + 3]);
                }
            }
        }

        float2 o0, o1;
#pragma unroll
        for (int j = 0; j < 2; j++) {
            float l0, h0, l1, h1, l2, h2, l3, h3;
            upk2(a[j][0], l0, h0); upk2(a[j][1], l1, h1);
            upk2(a[j][2], l2, h2); upk2(a[j][3], l3, h3);
            float m0 = fmaxf(fmaxf(l0, l1), fmaxf(l2, l3));
            float m1 = fmaxf(fmaxf(h0, h1), fmaxf(h2, h3));
            m0 = fmaxf(m0 + bias2.x, 0.f);   // max(relu(x+b)) == relu(max+b)
            m1 = fmaxf(m1 + bias2.y, 0.f);
            if (!interior) {
                int rs = r0s + r, cs = c0s + 2 * cp + j;
                if ((unsigned)rs >= 128u || (unsigned)cs >= 128u) { m0 = 0.f; m1 = 0.f; }
            }
            ((float*)&o0)[j] = m0;
            ((float*)&o1)[j] = m1;
        }
        *(float2*)&d0[r][2 * cp] = o0;
        *(float2*)&d1[r][2 * cp] = o1;

        cp += 9; r += 7;                 // advance 128 = 7*17 + 9
        if (cp >= 17) { cp -= 17; r++; }
    }
}

// ---------------------------------------------------------------------------
// conv2 stage: accumulate one input channel. Rolling 2-row broadcast buffer;
// oc-pairs in f32x2 lanes. Weights via LDS.128.
// ---------------------------------------------------------------------------
__device__ __forceinline__ void conv2_stage(
    const float (*src)[36], const ull* __restrict__ wrow,
    int tx, int ty, ull acc[4][4])
{
    ull rA[4], rB[4];
    {
        float2 v0 = *(const float2*)&src[2 * ty][2 * tx];
        float2 v1 = *(const float2*)&src[2 * ty][2 * tx + 2];
        rA[0] = pk2(v0.x, v0.x); rA[1] = pk2(v0.y, v0.y);
        rA[2] = pk2(v1.x, v1.x); rA[3] = pk2(v1.y, v1.y);
    }
#pragma unroll
    for (int ky = 0; ky < 3; ky++) {
        ull* top = (ky & 1) ? rB : rA;
        ull* bot = (ky & 1) ? rA : rB;
        {
            float2 v0 = *(const float2*)&src[2 * ty + ky + 1][2 * tx];
            float2 v1 = *(const float2*)&src[2 * ty + ky + 1][2 * tx + 2];
            bot[0] = pk2(v0.x, v0.x); bot[1] = pk2(v0.y, v0.y);
            bot[2] = pk2(v1.x, v1.x); bot[3] = pk2(v1.y, v1.y);
        }
#pragma unroll
        for (int kx = 0; kx < 3; kx++) {
            ulonglong2 wa = *(const ulonglong2*)&wrow[(ky * 3 + kx) * 4];
            ulonglong2 wb = *(const ulonglong2*)&wrow[(ky * 3 + kx) * 4 + 2];
#pragma unroll
            for (int dx = 0; dx < 2; dx++) {
                ull pt = top[dx + kx];
                ull pb = bot[dx + kx];
                fma2(acc[dx][0], wa.x, pt);
                fma2(acc[dx][1], wa.y, pt);
                fma2(acc[dx][2], wb.x, pt);
                fma2(acc[dx][3], wb.y, pt);
                fma2(acc[2 + dx][0], wa.x, pb);
                fma2(acc[2 + dx][1], wa.y, pb);
                fma2(acc[2 + dx][2], wb.x, pb);
                fma2(acc[2 + dx][3], wb.y, pb);
            }
        }
    }
}

// ---------------------------------------------------------------------------
// PERSISTENT FUSED KERNEL: 1184 CTAs (8/SM), each loops over 2-3 tiles.
// Per tile: DWT fill (overlaps previous tile's conv2/epilogue) ->
// conv1+relu+pool -> conv2+relu+pool -> conv3(1x1).
// Weight smem prep once per CTA.
// ---------------------------------------------------------------------------
__global__ void __launch_bounds__(128, 8) fused_kernel(
    const float* __restrict__ x,
    const float* __restrict__ w1, const float* __restrict__ b1,
    const float* __restrict__ w2, const float* __restrict__ b2,
    const float* __restrict__ w3, const float* __restrict__ b3,
    float* __restrict__ low, float* __restrict__ high)
{
    __shared__ __align__(16) float cAt[38][72];      // 10.9 KB
    __shared__ __align__(16) float s1t[4][18][36];   // 10.4 KB
    __shared__ __align__(16) ull    w2p[16 * 9 * 4]; //  4.6 KB
    __shared__ __align__(16) ull    w1p[8 * 10];     //  640 B
    __shared__ float2 b1p[8];
    __shared__ float  b2s[8];
    __shared__ float  w3s[32];
    __shared__ float  b3s[4];

    const int tx = threadIdx.x, ty = threadIdx.y;    // block (16, 8)
    const int tid = ty * 16 + tx;

    // ---- weights to smem: ONCE per CTA ----
    if (tid < 80) {
        int icp = tid / 10, k = tid - 10 * icp;
        w1p[tid] = (k < 9) ? pk2(w1[(2 * icp) * 9 + k], w1[(2 * icp + 1) * 9 + k]) : 0ull;
    }
    if (tid < 8)  b1p[tid] = make_float2(b1[2 * tid], b1[2 * tid + 1]);
    if (tid < 8)  b2s[tid] = b2[tid];
    if (tid < 32) w3s[tid] = w3[tid];
    if (tid < 4)  b3s[tid] = b3[tid];
    for (int idx = tid; idx < 16 * 9 * 4; idx += 128) {
        int ocp = idx & 3;
        int k   = (idx >> 2) % 9;
        int ic  = idx / 36;
        int oc0 = 2 * ocp;
        float lo = w2[(oc0 * 16 + ic) * 9 + k];
        float hi = w2[((oc0 + 1) * 16 + ic) * 9 + k];
        w2p[idx] = pk2(lo, hi);
    }

    for (int tile = blockIdx.x; tile < NTILES; tile += NCTA) {
        const int img = tile >> 5;
        const int rem = tile & 31;
        const int py0 = (rem >> 2) * 8;               // pooled-64 row origin
        const int px0 = (rem & 3) * 16;               // pooled-64 col origin

        // ---- DWT fill: cA 38x70 tile; cH/cV for owned 64x32 -> high ----
        // Safe without a leading barrier: after the last round's mid-sync all
        // warps are past conv1 (last cAt reads); conv2/epilogue touch only
        // s1t/registers. The round-0 sync below orders fill -> conv1.
        {
            const float* xin = x + (size_t)img * HH * WW;
            float* hp = high + (size_t)img * (2 * HS * WS);
            const int gr0 = 4 * py0 - 3, gc0 = 4 * px0 - 3;  // cA-space origin
            int r = tid / 70, c = tid - 70 * r;
            for (int k = tid; k < 38 * 70; k += 128) {
                int ir = gr0 + r, ic = gc0 + c;              // cA coords
                float va = 0.f, vh = 0.f, vv = 0.f;
                if ((unsigned)ir < (unsigned)HS && (unsigned)ic < (unsigned)WS) {
                    const float* p0 = xin + (size_t)(2 * ir) * WW + 2 * ic;
                    float2 q0 = *(const float2*)p0;
                    float2 q1 = *(const float2*)(p0 + WW);
                    float s0 = q0.x + q0.y, s1 = q1.x + q1.y;
                    float e0 = q0.x - q0.y, e1 = q1.x - q1.y;
                    va = 0.5f * (s0 + s1);
                    vh = 0.5f * (s0 - s1);
                    vv = 0.5f * (e0 + e1);
                }
                cAt[r][c] = va;
                if (r >= 3 && r < 35 && c >= 3 && c < 67) {  // owned region
                    int o = ir * WS + ic;
                    hp[o] = vh;
                    hp[HS * WS + o] = vv;
                }
                c += 58; r += 1;                 // advance 128 = 1*70 + 58
                if (c >= 70) { c -= 70; r++; }
            }
        }

        const int r0s = 2 * py0 - 1, c0s = 2 * px0 - 1;
        const bool interior = (py0 >= 8 && py0 <= 48) && (px0 == 16 || px0 == 32);

        ull acc[4][4];
#pragma unroll
        for (int q = 0; q < 4; q++)
#pragma unroll
            for (int p = 0; p < 4; p++) acc[q][p] = 0ull;

        for (int rnd = 0; rnd < 4; rnd++) {
            __syncthreads();   // orders: fill->conv1, prev conv2->s1t overwrite
            const int tA = (tid + rnd * 32) & 127;
            const int tB = (tid + rnd * 32 + 64) & 127;
            conv1_pair((const float(*)[72])cAt, s1t[0], s1t[1],
                       &w1p[(2 * rnd) * 10],     b1p[2 * rnd],     tA, r0s, c0s, interior);
            conv1_pair((const float(*)[72])cAt, s1t[2], s1t[3],
                       &w1p[(2 * rnd + 1) * 10], b1p[2 * rnd + 1], tB, r0s, c0s, interior);
            __syncthreads();
#pragma unroll
            for (int j = 0; j < 4; j++)
                conv2_stage((const float(*)[36])s1t[j], &w2p[(4 * rnd + j) * 36], tx, ty, acc);
        }

        // ---- epilogue: bias + pool-max + relu, then 1x1 conv3 ----
        float r8[8];
#pragma unroll
        for (int p = 0; p < 4; p++) {
            float lo0, hi0, lo1, hi1, lo2, hi2, lo3, hi3;
            upk2(acc[0][p], lo0, hi0);
            upk2(acc[1][p], lo1, hi1);
            upk2(acc[2][p], lo2, hi2);
            upk2(acc[3][p], lo3, hi3);
            float mlo = fmaxf(fmaxf(lo0, lo1), fmaxf(lo2, lo3));
            float mhi = fmaxf(fmaxf(hi0, hi1), fmaxf(hi2, hi3));
            r8[2 * p]     = fmaxf(mlo + b2s[2 * p], 0.f);
            r8[2 * p + 1] = fmaxf(mhi + b2s[2 * p + 1], 0.f);
        }

        const int pix = (py0 + ty) * 64 + px0 + tx;
        float* lp = low + (size_t)img * 4 * 4096 + pix;
#pragma unroll
        for (int oc = 0; oc < 4; oc++) {
            float s = b3s[oc];
#pragma unroll
            for (int ic = 0; ic < 8; ic++) s = fmaf(w3s[oc * 8 + ic], r8[ic], s);
            lp[oc * 4096] = s;
        }
    }
}

// ---------------------------------------------------------------------------
extern "C" void kernel_launch(void* const* d_in, const int* in_sizes, int n_in,
                              void* d_out, int out_size) {
    const float* x  = (const float*)d_in[0];
    const float* w1 = (const float*)d_in[1];
    const float* b1 = (const float*)d_in[2];
    const float* w2 = (const float*)d_in[3];
    const float* b2 = (const float*)d_in[4];
    const float* w3 = (const float*)d_in[5];
    const float* b3 = (const float*)d_in[6];

    float* out  = (float*)d_out;
    float* low  = out;                    // 96*4*64*64 = 1,572,864 floats
    float* high = out + 1572864;          // 96*2*256*256 = 12,582,912 floats

    fused_kernel<<<NCTA, dim3(16, 8)>>>(x, w1, b1, w2, b2, w3, b3, low, high);
}